// round 14
// baseline (speedup 1.0000x reference)
#include <cuda_runtime.h>
#include <cuda_fp16.h>
#include <cstdint>
#include <cstddef>

// Problem constants
constexpr int Nn = 100000;   // nodes
constexpr int NPAD = 100096; // Nn rounded up to 128 (GEMM tile rows)
constexpr int Ee = 500000;   // edges per relation
constexpr int Rr = 3;        // relations
constexpr int Ll = 2;        // layers
constexpr int Ff = 300;      // input features
constexpr int Hh = 256;      // hidden
constexpr int Cc = 23;       // classes
constexpr int NSEG = Rr * Nn;    // 300000 CSR segments

// -------- device scratch (static globals: no runtime allocation) --------
__device__ float g_acc0[(size_t)NPAD * Hh];         // pre-BN activations (ping)
__device__ float g_acc1[(size_t)NPAD * Hh];         // pre-BN activations (pong)
__device__ __align__(16) __half g_m16[(size_t)NPAD * 3 * Hh]; // gathered messages fp16
__device__ int   g_dout[Rr * Nn];
__device__ int   g_din[Rr * Nn];
__device__ int   g_off[NSEG + 1];                   // CSR offsets by (r, dst)
__device__ int   g_cursor[NSEG];
__device__ int   g_csrc[Rr * Ee];                   // CSR-ordered src
__device__ float g_ccoef[Rr * Ee];                  // CSR-ordered coef
__device__ int   g_bsum[512];                       // scan block partials
__device__ float g_bias[Hh];                        // combined skip+mean(gcn) bias
__device__ float g_sum[Hh];
__device__ float g_sq[Hh];
__device__ float g_scale[Hh];
__device__ float g_shift[Hh];
__device__ __align__(16) __half g_Bt[256 * 1024];   // transposed fp16 weights [256, Kpad]

// =====================  misc small kernels  =====================
__global__ void zero_k(float4* __restrict__ p, int n4) {
    int i = blockIdx.x * blockDim.x + threadIdx.x;
    int stride = gridDim.x * blockDim.x;
    float4 z = make_float4(0.f, 0.f, 0.f, 0.f);
    for (; i < n4; i += stride) p[i] = z;
}

__global__ void deg_k(const int* __restrict__ src, const int* __restrict__ dst,
                      int* __restrict__ doutA, int* __restrict__ dinA) {
    int i = blockIdx.x * blockDim.x + threadIdx.x;
    if (i >= Rr * Ee) return;
    int r = i / Ee;
    atomicAdd(&doutA[r * Nn + src[i]], 1);
    atomicAdd(&dinA[r * Nn + dst[i]], 1);
}

// ---------------- CSR build: 3-kernel exclusive scan + fill ----------------
__global__ void scan1_k(const int* __restrict__ cnt, int* __restrict__ off,
                        int* __restrict__ bsum, int n) {
    __shared__ int wt[32];
    int tid = threadIdx.x, lane = tid & 31, wid = tid >> 5;
    int i = blockIdx.x * 1024 + tid;
    int v = (i < n) ? cnt[i] : 0;
    int x = v;
#pragma unroll
    for (int d = 1; d < 32; d <<= 1) {
        int y = __shfl_up_sync(0xffffffffu, x, d);
        if (lane >= d) x += y;
    }
    if (lane == 31) wt[wid] = x;
    __syncthreads();
    if (wid == 0) {
        int t = wt[lane];
        int tx = t;
#pragma unroll
        for (int d = 1; d < 32; d <<= 1) {
            int y = __shfl_up_sync(0xffffffffu, tx, d);
            if (lane >= d) tx += y;
        }
        wt[lane] = tx - t;   // exclusive
    }
    __syncthreads();
    int excl = wt[wid] + x - v;
    if (i < n) off[i] = excl;
    if (tid == 1023) bsum[blockIdx.x] = excl + v;
}

__global__ void scan2_k(int* __restrict__ bsum, int* __restrict__ off, int nb, int n) {
    __shared__ int wt[32];
    int tid = threadIdx.x, lane = tid & 31, wid = tid >> 5;
    int v = (tid < nb) ? bsum[tid] : 0;
    int x = v;
#pragma unroll
    for (int d = 1; d < 32; d <<= 1) {
        int y = __shfl_up_sync(0xffffffffu, x, d);
        if (lane >= d) x += y;
    }
    if (lane == 31) wt[wid] = x;
    __syncthreads();
    if (wid == 0) {
        int t = wt[lane];
        int tx = t;
#pragma unroll
        for (int d = 1; d < 32; d <<= 1) {
            int y = __shfl_up_sync(0xffffffffu, tx, d);
            if (lane >= d) tx += y;
        }
        wt[lane] = tx - t;
    }
    __syncthreads();
    int excl = wt[wid] + x - v;
    if (tid < nb) bsum[tid] = excl;
    if (tid == nb - 1) off[n] = excl + v;   // grand total
}

__global__ void addback_k(int* __restrict__ off, int* __restrict__ cursor,
                          const int* __restrict__ bsum, int n) {
    int i = blockIdx.x * blockDim.x + threadIdx.x;
    if (i >= n) return;
    int v = off[i] + bsum[i >> 10];
    off[i] = v;
    cursor[i] = v;
}

// fill with inlined coefficient computation (removes coef_k pass)
__global__ void fill_k(const int* __restrict__ src, const int* __restrict__ dst,
                       const int* __restrict__ doutA, const int* __restrict__ dinA,
                       int* __restrict__ cursor,
                       int* __restrict__ csrc, float* __restrict__ ccoef) {
    int i = blockIdx.x * blockDim.x + threadIdx.x;
    if (i >= Rr * Ee) return;
    int r = i / Ee;
    int s = src[i], dd = dst[i];
    float o = (float)max(doutA[r * Nn + s], 1);
    float d = (float)max(dinA[r * Nn + dd], 1);
    float c = rsqrtf(o) * rsqrtf(d) * (1.f / 3.f);
    int pos = atomicAdd(&cursor[r * Nn + dd], 1);
    csrc[pos] = s;
    ccoef[pos] = c;
}

// Gather with inline BN+activation: one warp per (relation, dst) segment.
// h[s][k] = act(fmaf(acc[s][k], scale[k], shift[k]))  — bit-identical to a
// separate bn_apply pass followed by the old gather.
template <int ACT>
__global__ void gather_k(const float* __restrict__ acc, const int* __restrict__ csrc,
                         const float* __restrict__ ccoef, const int* __restrict__ off,
                         __half* __restrict__ m16) {
    int warp = (blockIdx.x * blockDim.x + threadIdx.x) >> 5;
    int lane = threadIdx.x & 31;
    if (warp >= NSEG) return;
    int r = warp / Nn;
    int dstn = warp - r * Nn;
    int e0 = off[warp], e1 = off[warp + 1];

    float4 sc0 = *(const float4*)&g_scale[lane * 4];
    float4 sh0 = *(const float4*)&g_shift[lane * 4];
    float4 sc1 = *(const float4*)&g_scale[128 + lane * 4];
    float4 sh1 = *(const float4*)&g_shift[128 + lane * 4];

    float4 a0 = make_float4(0.f, 0.f, 0.f, 0.f);
    float4 a1 = make_float4(0.f, 0.f, 0.f, 0.f);
    for (int e = e0; e < e1; e++) {
        int s = __ldg(&csrc[e]);
        float c = __ldg(&ccoef[e]);
        const float4* hr = (const float4*)(acc + (size_t)s * Hh);
        float4 v0 = hr[lane];
        float4 v1 = hr[lane + 32];
        v0.x = fmaf(v0.x, sc0.x, sh0.x); v0.y = fmaf(v0.y, sc0.y, sh0.y);
        v0.z = fmaf(v0.z, sc0.z, sh0.z); v0.w = fmaf(v0.w, sc0.w, sh0.w);
        v1.x = fmaf(v1.x, sc1.x, sh1.x); v1.y = fmaf(v1.y, sc1.y, sh1.y);
        v1.z = fmaf(v1.z, sc1.z, sh1.z); v1.w = fmaf(v1.w, sc1.w, sh1.w);
        if (ACT == 0) {
            v0.x = fmaxf(v0.x, 0.f); v0.y = fmaxf(v0.y, 0.f);
            v0.z = fmaxf(v0.z, 0.f); v0.w = fmaxf(v0.w, 0.f);
            v1.x = fmaxf(v1.x, 0.f); v1.y = fmaxf(v1.y, 0.f);
            v1.z = fmaxf(v1.z, 0.f); v1.w = fmaxf(v1.w, 0.f);
        } else {
            v0.x = (v0.x > 0.f) ? v0.x : 0.01f * v0.x;
            v0.y = (v0.y > 0.f) ? v0.y : 0.01f * v0.y;
            v0.z = (v0.z > 0.f) ? v0.z : 0.01f * v0.z;
            v0.w = (v0.w > 0.f) ? v0.w : 0.01f * v0.w;
            v1.x = (v1.x > 0.f) ? v1.x : 0.01f * v1.x;
            v1.y = (v1.y > 0.f) ? v1.y : 0.01f * v1.y;
            v1.z = (v1.z > 0.f) ? v1.z : 0.01f * v1.z;
            v1.w = (v1.w > 0.f) ? v1.w : 0.01f * v1.w;
        }
        a0.x = fmaf(c, v0.x, a0.x); a0.y = fmaf(c, v0.y, a0.y);
        a0.z = fmaf(c, v0.z, a0.z); a0.w = fmaf(c, v0.w, a0.w);
        a1.x = fmaf(c, v1.x, a1.x); a1.y = fmaf(c, v1.y, a1.y);
        a1.z = fmaf(c, v1.z, a1.z); a1.w = fmaf(c, v1.w, a1.w);
    }
    __half* md = m16 + (size_t)dstn * (3 * Hh) + r * Hh;
    __half2 p0 = __floats2half2_rn(a0.x, a0.y);
    __half2 p1 = __floats2half2_rn(a0.z, a0.w);
    __half2 p2 = __floats2half2_rn(a1.x, a1.y);
    __half2 p3 = __floats2half2_rn(a1.z, a1.w);
    *(uint2*)(md + lane * 4) = make_uint2(*(uint32_t*)&p0, *(uint32_t*)&p1);
    *(uint2*)(md + 128 + lane * 4) = make_uint2(*(uint32_t*)&p2, *(uint32_t*)&p3);
}

__global__ void bias_k(const float* __restrict__ skip_b,
                       const float* __restrict__ gcn_b,
                       float* __restrict__ bias) {
    int t = threadIdx.x;
    bias[t] = skip_b[t] + (gcn_b[t] + gcn_b[Hh + t] + gcn_b[2 * Hh + t]) * (1.f / 3.f);
}

// Transpose + fp32->fp16 weight prep: Bt[n, k] = W[k, n], zero-padded to Kpad
__global__ void wprep_k(const float* __restrict__ W, __half* __restrict__ Bt,
                        int K, int Kpad) {
    int i = blockIdx.x * blockDim.x + threadIdx.x;
    if (i >= 256 * Kpad) return;
    int n = i / Kpad, k = i % Kpad;
    Bt[i] = (k < K) ? __float2half_rn(W[(size_t)k * 256 + n]) : __float2half_rn(0.f);
}

// Combined layer weights: Bt[n, k] = gcn slab (k<768) | skip_W (k>=768)
__global__ void wprep_layer_k(const float* __restrict__ gcnW,
                              const float* __restrict__ skipW,
                              __half* __restrict__ Bt) {
    int i = blockIdx.x * blockDim.x + threadIdx.x;
    if (i >= 256 * 1024) return;
    int n = i >> 10, k = i & 1023;
    float v = (k < 768) ? gcnW[(size_t)k * 256 + n] : skipW[(size_t)(k - 768) * 256 + n];
    Bt[i] = __float2half_rn(v);
}

// =====================  mma.sync fp16 GEMM (pipelined, fused BN-load + BN stats)  =========
// MODE 0 (FEAT):  A = fp32 x [M,300] -> fp16 on load; Kpad=320.
// MODE 1 (LAYER): chunks 0..11 A = m16 (cp.async), chunks 12..15 A = BN(accsrc).
// MODE 2 (HEAD):  A = BN(accsrc), Kpad=256.
// BN(acc): v = act(fmaf(v, scale, shift)) then cvt fp16 — bit-identical to old bn_apply+h16.
// Grid (2, gx): N-tiles adjacent in bid order -> A tile L2 reuse.

__device__ __forceinline__ uint32_t smem_u32(const void* p) {
    uint32_t a;
    asm("{ .reg .u64 t; cvta.to.shared.u64 t, %1; cvt.u32.u64 %0, t; }" : "=r"(a) : "l"(p));
    return a;
}

__device__ __forceinline__ uint32_t swz(uint32_t base, int row, int k) {
    return base + row * 128 + ((((k >> 3) ^ row) & 7) << 4) + (k & 7) * 2;
}

__device__ __forceinline__ void ldmx4(uint32_t* r, uint32_t addr) {
    asm volatile("ldmatrix.sync.aligned.m8n8.x4.shared.b16 {%0,%1,%2,%3}, [%4];"
                 : "=r"(r[0]), "=r"(r[1]), "=r"(r[2]), "=r"(r[3]) : "r"(addr));
}

__device__ __forceinline__ void mma16816(float* d, const uint32_t* a, const uint32_t* b) {
    asm volatile(
        "mma.sync.aligned.m16n8k16.row.col.f32.f16.f16.f32 "
        "{%0,%1,%2,%3}, {%4,%5,%6,%7}, {%8,%9}, {%0,%1,%2,%3};"
        : "+f"(d[0]), "+f"(d[1]), "+f"(d[2]), "+f"(d[3])
        : "r"(a[0]), "r"(a[1]), "r"(a[2]), "r"(a[3]), "r"(b[0]), "r"(b[1]));
}

constexpr int GEMM_SMEM = 65536 + 2048;   // 2x16KB A | 2x16KB B | scale+shift

template <int MODE, int ACT, bool STATS>
__global__ void __launch_bounds__(256)
gemm_mma_k(const __half* __restrict__ Am, const float* __restrict__ Af,
           const __half* __restrict__ Bt, const float* __restrict__ bias,
           float* __restrict__ C, int M, int Kpad) {
    extern __shared__ __align__(16) char smem[];
    const uint32_t SA0 = smem_u32(smem);
    const uint32_t SB0 = SA0 + 32768;
    float* ssc = (float*)(smem + 65536);
    float* ssh = ssc + 256;

    const int tid = threadIdx.x;
    const int lane = tid & 31;
    const int w = tid >> 5;
    const int wm = (w & 3) * 32;
    const int wn = (w >> 2) * 64;
    const int bn = blockIdx.x * 128;   // N tile (fast dim -> A reuse in L2)
    const int bm = blockIdx.y * 128;   // M tile

    if (MODE != 0) {
        if (tid < 256) { ssc[tid] = g_scale[tid]; ssh[tid] = g_shift[tid]; }
        __syncthreads();
    }

    float d[2][8][4];
#pragma unroll
    for (int i = 0; i < 2; i++)
#pragma unroll
        for (int j = 0; j < 8; j++)
#pragma unroll
            for (int t = 0; t < 4; t++) d[i][j][t] = 0.f;

    const int a_r = lane & 15;
    const int a_k = (lane >> 4) * 8;
    const int b_r = (lane & 7) + ((lane & 16) ? 8 : 0);
    const int b_k = (lane & 8) ? 8 : 0;

    const int nk = Kpad / 64;
    float4 ra[8];

    auto viaRegs = [](int c) {
        return MODE == 0 || MODE == 2 || (MODE == 1 && c >= 12);
    };

    auto ldgA = [&](int c) {
#pragma unroll
        for (int t = 0; t < 4; t++) {
            int u = tid + t * 256;
            int row = u >> 3, c8 = (u & 7) * 8;
            int gr = bm + row;
            float4 v0 = make_float4(0.f, 0.f, 0.f, 0.f);
            float4 v1 = v0;
            if (MODE == 0) {
                if (gr < M) {
                    int gk = c * 64 + c8;
                    if (gk < Ff)     v0 = *(const float4*)(Af + (size_t)gr * Ff + gk);
                    if (gk + 4 < Ff) v1 = *(const float4*)(Af + (size_t)gr * Ff + gk + 4);
                }
            } else {
                if (gr < M) {
                    int kb = ((MODE == 1) ? (c - 12) * 64 : c * 64) + c8;
                    const float* ar = Af + (size_t)gr * 256 + kb;
                    v0 = *(const float4*)ar;
                    v1 = *(const float4*)(ar + 4);
                    float4 s0 = *(const float4*)&ssc[kb],     h0 = *(const float4*)&ssh[kb];
                    float4 s1 = *(const float4*)&ssc[kb + 4], h1 = *(const float4*)&ssh[kb + 4];
                    v0.x = fmaf(v0.x, s0.x, h0.x); v0.y = fmaf(v0.y, s0.y, h0.y);
                    v0.z = fmaf(v0.z, s0.z, h0.z); v0.w = fmaf(v0.w, s0.w, h0.w);
                    v1.x = fmaf(v1.x, s1.x, h1.x); v1.y = fmaf(v1.y, s1.y, h1.y);
                    v1.z = fmaf(v1.z, s1.z, h1.z); v1.w = fmaf(v1.w, s1.w, h1.w);
                    if (ACT == 0) {
                        v0.x = fmaxf(v0.x, 0.f); v0.y = fmaxf(v0.y, 0.f);
                        v0.z = fmaxf(v0.z, 0.f); v0.w = fmaxf(v0.w, 0.f);
                        v1.x = fmaxf(v1.x, 0.f); v1.y = fmaxf(v1.y, 0.f);
                        v1.z = fmaxf(v1.z, 0.f); v1.w = fmaxf(v1.w, 0.f);
                    } else {
                        v0.x = (v0.x > 0.f) ? v0.x : 0.01f * v0.x;
                        v0.y = (v0.y > 0.f) ? v0.y : 0.01f * v0.y;
                        v0.z = (v0.z > 0.f) ? v0.z : 0.01f * v0.z;
                        v0.w = (v0.w > 0.f) ? v0.w : 0.01f * v0.w;
                        v1.x = (v1.x > 0.f) ? v1.x : 0.01f * v1.x;
                        v1.y = (v1.y > 0.f) ? v1.y : 0.01f * v1.y;
                        v1.z = (v1.z > 0.f) ? v1.z : 0.01f * v1.z;
                        v1.w = (v1.w > 0.f) ? v1.w : 0.01f * v1.w;
                    }
                }
            }
            ra[t * 2 + 0] = v0;
            ra[t * 2 + 1] = v1;
        }
    };

    auto stsA = [&](int stage) {
        const uint32_t SA = SA0 + stage * 16384;
#pragma unroll
        for (int t = 0; t < 4; t++) {
            int u = tid + t * 256;
            int row = u >> 3, c8 = (u & 7) * 8;
            float4 v0 = ra[t * 2 + 0];
            float4 v1 = ra[t * 2 + 1];
            __half2 h0 = __floats2half2_rn(v0.x, v0.y);
            __half2 h1 = __floats2half2_rn(v0.z, v0.w);
            __half2 h2 = __floats2half2_rn(v1.x, v1.y);
            __half2 h3 = __floats2half2_rn(v1.z, v1.w);
            uint32_t o0 = *(uint32_t*)&h0, o1 = *(uint32_t*)&h1;
            uint32_t o2 = *(uint32_t*)&h2, o3 = *(uint32_t*)&h3;
            asm volatile("st.shared.v4.b32 [%0], {%1,%2,%3,%4};"
                         :: "r"(swz(SA, row, c8)), "r"(o0), "r"(o1), "r"(o2), "r"(o3)
                         : "memory");
        }
    };

    auto loadNext = [&](int c, int stage) {
        const int k0 = c * 64;
        const uint32_t SB = SB0 + stage * 16384;
#pragma unroll
        for (int t = 0; t < 4; t++) {
            int u = tid + t * 256;
            int row = u >> 3, c8 = (u & 7) * 8;
            const void* gb = Bt + (size_t)(bn + row) * Kpad + k0 + c8;
            asm volatile("cp.async.cg.shared.global [%0], [%1], 16;"
                         :: "r"(swz(SB, row, c8)), "l"(gb) : "memory");
        }
        if (MODE == 1 && c < 12) {
            const uint32_t SA = SA0 + stage * 16384;
#pragma unroll
            for (int t = 0; t < 4; t++) {
                int u = tid + t * 256;
                int row = u >> 3, c8 = (u & 7) * 8;
                const void* ga = Am + (size_t)(bm + row) * 768 + k0 + c8;
                asm volatile("cp.async.cg.shared.global [%0], [%1], 16;"
                             :: "r"(swz(SA, row, c8)), "l"(ga) : "memory");
            }
        }
        asm volatile("cp.async.commit_group;" ::: "memory");
        if (viaRegs(c)) ldgA(c);
    };

    loadNext(0, 0);

    for (int c = 0; c < nk; c++) {
        const int stage = c & 1;
        if (viaRegs(c)) stsA(stage);
        asm volatile("cp.async.wait_group 0;" ::: "memory");
        __syncthreads();
        if (c + 1 < nk) loadNext(c + 1, stage ^ 1);
        const uint32_t SA = SA0 + stage * 16384;
        const uint32_t SB = SB0 + stage * 16384;
#pragma unroll
        for (int ks = 0; ks < 64; ks += 16) {
            uint32_t afr[2][4];
#pragma unroll
            for (int mi = 0; mi < 2; mi++)
                ldmx4(afr[mi], swz(SA, wm + mi * 16 + a_r, ks + a_k));
#pragma unroll
            for (int np = 0; np < 4; np++) {
                uint32_t bfr[4];
                ldmx4(bfr, swz(SB, wn + np * 16 + b_r, ks + b_k));
#pragma unroll
                for (int mi = 0; mi < 2; mi++) {
                    mma16816(d[mi][np * 2 + 0], afr[mi], bfr + 0);
                    mma16816(d[mi][np * 2 + 1], afr[mi], bfr + 2);
                }
            }
        }
    }

    // ---- epilogue: bias + store + fused BN stats ----
    const int er = lane >> 2;
    const int ec = (lane & 3) * 2;
#pragma unroll
    for (int mi = 0; mi < 2; mi++) {
#pragma unroll
        for (int half = 0; half < 2; half++) {
            int gr = bm + wm + mi * 16 + er + half * 8;
            bool ok = gr < M;
            float* crow = C + (size_t)gr * 256;
#pragma unroll
            for (int ni = 0; ni < 8; ni++) {
                int gc = bn + wn + ni * 8 + ec;
                float v0 = d[mi][ni][half * 2 + 0];
                float v1 = d[mi][ni][half * 2 + 1];
                if (bias) { v0 += bias[gc]; v1 += bias[gc + 1]; }
                if (ok) {
                    *(float2*)(crow + gc) = make_float2(v0, v1);
                } else {
                    v0 = 0.f; v1 = 0.f;
                }
                if (STATS) {
                    d[mi][ni][half * 2 + 0] = v0;
                    d[mi][ni][half * 2 + 1] = v1;
                }
            }
        }
    }
    if (STATS) {
#pragma unroll
        for (int ni = 0; ni < 8; ni++) {
            float s0 = 0.f, q0 = 0.f, s1 = 0.f, q1 = 0.f;
#pragma unroll
            for (int mi = 0; mi < 2; mi++)
#pragma unroll
                for (int half = 0; half < 2; half++) {
                    float v0 = d[mi][ni][half * 2 + 0];
                    float v1 = d[mi][ni][half * 2 + 1];
                    s0 += v0; q0 = fmaf(v0, v0, q0);
                    s1 += v1; q1 = fmaf(v1, v1, q1);
                }
#pragma unroll
            for (int o = 4; o <= 16; o <<= 1) {
                s0 += __shfl_xor_sync(0xffffffffu, s0, o);
                q0 += __shfl_xor_sync(0xffffffffu, q0, o);
                s1 += __shfl_xor_sync(0xffffffffu, s1, o);
                q1 += __shfl_xor_sync(0xffffffffu, q1, o);
            }
            if (lane < 4) {
                int gc = bn + wn + ni * 8 + ec;
                atomicAdd(&g_sum[gc], s0);
                atomicAdd(&g_sq[gc], q0);
                atomicAdd(&g_sum[gc + 1], s1);
                atomicAdd(&g_sq[gc + 1], q1);
            }
        }
    }
}

// =====================  head2: out = relu(bn(acc)) @ W_c2 + b  =====================
constexpr int H2_SMEM = 64 * 257 * 4 + 256 * 24 * 4;

__global__ void __launch_bounds__(256)
head2_k(const float* __restrict__ acc, const float* __restrict__ W,
        const float* __restrict__ b, float* __restrict__ out, int M) {
    extern __shared__ float sm[];
    float* tile = sm;              // [64][257] transposed chunk (post-BN)
    float* Bs = sm + 64 * 257;     // [256][24]
    const int tid = threadIdx.x;
    const int r0 = blockIdx.x * 256;

    for (int i = tid; i < 256 * 24; i += 256) {
        int k = i / 24, c = i - k * 24;
        Bs[i] = (c < Cc) ? W[k * Cc + c] : 0.f;
    }

    float acc_[24];
#pragma unroll
    for (int c = 0; c < 24; c++) acc_[c] = 0.f;

    for (int k0 = 0; k0 < 256; k0 += 64) {
        __syncthreads();
        for (int f = tid; f < 4096; f += 256) {
            int row = f >> 4, c4 = (f & 15) << 2;
            int gr = r0 + row;
            float4 v = make_float4(0.f, 0.f, 0.f, 0.f);
            if (gr < M) {
                v = *(const float4*)(acc + (size_t)gr * 256 + k0 + c4);
                float4 s4 = *(const float4*)&g_scale[k0 + c4];
                float4 h4 = *(const float4*)&g_shift[k0 + c4];
                v.x = fmaxf(fmaf(v.x, s4.x, h4.x), 0.f);
                v.y = fmaxf(fmaf(v.y, s4.y, h4.y), 0.f);
                v.z = fmaxf(fmaf(v.z, s4.z, h4.z), 0.f);
                v.w = fmaxf(fmaf(v.w, s4.w, h4.w), 0.f);
            }
            tile[(c4 + 0) * 257 + row] = v.x;
            tile[(c4 + 1) * 257 + row] = v.y;
            tile[(c4 + 2) * 257 + row] = v.z;
            tile[(c4 + 3) * 257 + row] = v.w;
        }
        __syncthreads();
#pragma unroll 4
        for (int k = 0; k < 64; k++) {
            float a = tile[k * 257 + tid];
            const float* br = Bs + (k0 + k) * 24;
#pragma unroll
            for (int c = 0; c < 24; c += 4) {
                float4 bv = *(const float4*)(br + c);
                acc_[c + 0] = fmaf(a, bv.x, acc_[c + 0]);
                acc_[c + 1] = fmaf(a, bv.y, acc_[c + 1]);
                acc_[c + 2] = fmaf(a, bv.z, acc_[c + 2]);
                acc_[c + 3] = fmaf(a, bv.w, acc_[c + 3]);
            }
        }
    }

    int gr = r0 + tid;
    if (gr < M) {
        float* orow = out + (size_t)gr * Cc;
#pragma unroll
        for (int c = 0; c < Cc; c++) orow[c] = acc_[c] + b[c];
    }
}

// =====================  BatchNorm stat kernels  =====================
__global__ void bn_zero_k() {
    int t = threadIdx.x;
    g_sum[t] = 0.f;
    g_sq[t] = 0.f;
}

__global__ void bn_final_k(const float* __restrict__ gamma,
                           const float* __restrict__ beta, float invM) {
    int t = threadIdx.x;
    float mean = g_sum[t] * invM;
    float var = fmaxf(g_sq[t] * invM - mean * mean, 0.f);
    float sc = gamma[t] * rsqrtf(var + 1e-5f);
    g_scale[t] = sc;
    g_shift[t] = beta[t] - mean * sc;
}

// =====================  host orchestration  =====================
extern "C" void kernel_launch(void* const* d_in, const int* in_sizes, int n_in,
                              void* d_out, int out_size) {
    (void)in_sizes; (void)n_in; (void)out_size;

    const float* x         = (const float*)d_in[0];
    const int*   esrc      = (const int*)d_in[1];
    const int*   edst      = (const int*)d_in[2];
    const float* W_feat    = (const float*)d_in[3];
    const float* b_feat    = (const float*)d_in[4];
    const float* g_feat    = (const float*)d_in[5];
    const float* beta_feat = (const float*)d_in[6];
    const float* gcn_W     = (const float*)d_in[7];
    const float* gcn_b     = (const float*)d_in[8];
    const float* skip_W    = (const float*)d_in[9];
    const float* skip_b    = (const float*)d_in[10];
    const float* bn_g      = (const float*)d_in[11];
    const float* bn_b      = (const float*)d_in[12];
    const float* W_c1      = (const float*)d_in[13];
    const float* b_c1      = (const float*)d_in[14];
    const float* g_c       = (const float*)d_in[15];
    const float* beta_c    = (const float*)d_in[16];
    const float* W_c2      = (const float*)d_in[17];
    const float* b_c2      = (const float*)d_in[18];
    float* out = (float*)d_out;

    float *acc0p, *acc1p, *biasp, *ccoefp;
    int *doutp, *dinp, *offp, *curp, *csrcp, *bsump;
    __half *btp, *m16p;
    cudaGetSymbolAddress((void**)&acc0p,  g_acc0);
    cudaGetSymbolAddress((void**)&acc1p,  g_acc1);
    cudaGetSymbolAddress((void**)&m16p,   g_m16);
    cudaGetSymbolAddress((void**)&biasp,  g_bias);
    cudaGetSymbolAddress((void**)&doutp,  g_dout);
    cudaGetSymbolAddress((void**)&dinp,   g_din);
    cudaGetSymbolAddress((void**)&offp,   g_off);
    cudaGetSymbolAddress((void**)&curp,   g_cursor);
    cudaGetSymbolAddress((void**)&csrcp,  g_csrc);
    cudaGetSymbolAddress((void**)&ccoefp, g_ccoef);
    cudaGetSymbolAddress((void**)&bsump,  g_bsum);
    cudaGetSymbolAddress((void**)&btp,    g_Bt);

    cudaFuncSetAttribute(gemm_mma_k<0, 0, true>, cudaFuncAttributeMaxDynamicSharedMemorySize, GEMM_SMEM);
    cudaFuncSetAttribute(gemm_mma_k<1, 0, true>, cudaFuncAttributeMaxDynamicSharedMemorySize, GEMM_SMEM);
    cudaFuncSetAttribute(gemm_mma_k<1, 1, true>, cudaFuncAttributeMaxDynamicSharedMemorySize, GEMM_SMEM);
    cudaFuncSetAttribute(gemm_mma_k<2, 1, true>, cudaFuncAttributeMaxDynamicSharedMemorySize, GEMM_SMEM);
    cudaFuncSetAttribute(head2_k, cudaFuncAttributeMaxDynamicSharedMemorySize, H2_SMEM);

    const int gx = (Nn + 127) / 128;                 // 782
    const dim3 mgrid(2, gx);                         // x = N tile, y = M tile
    const int eblocks = (Rr * Ee + 255) / 256;
    const int nscan = (NSEG + 1023) / 1024;          // 293

    // ---- degrees + CSR with inlined (src, coef) payload ----
    zero_k<<<512, 256>>>((float4*)doutp, Rr * Nn / 4);
    zero_k<<<512, 256>>>((float4*)dinp,  Rr * Nn / 4);
    deg_k<<<eblocks, 256>>>(esrc, edst, doutp, dinp);
    scan1_k<<<nscan, 1024>>>(dinp, offp, bsump, NSEG);
    scan2_k<<<1, 1024>>>(bsump, offp, nscan, NSEG);
    addback_k<<<(NSEG + 255) / 256, 256>>>(offp, curp, bsump, NSEG);
    fill_k<<<eblocks, 256>>>(esrc, edst, doutp, dinp, curp, csrcp, ccoefp);

    // ---- feat_reduce: Linear (mma from fp32 x, fused stats) ----
    wprep_k<<<(256 * 320 + 255) / 256, 256>>>(W_feat, btp, Ff, 320);
    bn_zero_k<<<1, 256>>>();
    gemm_mma_k<0, 0, true><<<mgrid, 256, GEMM_SMEM>>>(nullptr, x, btp, b_feat, acc0p, Nn, 320);
    bn_final_k<<<1, 256>>>(g_feat, beta_feat, 1.f / Nn);

    // ---- GCN layers: fused skip+relation GEMM (K=1024), BN inline everywhere ----
    {
        // layer 0: reads acc0 (feat BN, ReLU) -> acc1
        bias_k<<<1, 256>>>(skip_b, gcn_b, biasp);
        wprep_layer_k<<<(256 * 1024 + 255) / 256, 256>>>(gcn_W, skip_W, btp);
        gather_k<0><<<(NSEG * 32 + 255) / 256, 256>>>(acc0p, csrcp, ccoefp, offp, m16p);
        bn_zero_k<<<1, 256>>>();
        gemm_mma_k<1, 0, true><<<mgrid, 256, GEMM_SMEM>>>(m16p, acc0p, btp, biasp, acc1p, Nn, 1024);
        bn_final_k<<<1, 256>>>(bn_g, bn_b, 1.f / Nn);
        // layer 1: reads acc1 (bn0, Leaky) -> acc0
        bias_k<<<1, 256>>>(skip_b + Hh, gcn_b + Rr * Hh, biasp);
        wprep_layer_k<<<(256 * 1024 + 255) / 256, 256>>>(
            gcn_W + (size_t)Rr * Hh * Hh, skip_W + (size_t)Hh * Hh, btp);
        gather_k<1><<<(NSEG * 32 + 255) / 256, 256>>>(acc1p, csrcp, ccoefp, offp, m16p);
        bn_zero_k<<<1, 256>>>();
        gemm_mma_k<1, 1, true><<<mgrid, 256, GEMM_SMEM>>>(m16p, acc1p, btp, biasp, acc0p, Nn, 1024);
        bn_final_k<<<1, 256>>>(bn_g + Hh, bn_b + Hh, 1.f / Nn);
    }

    // ---- classification head ----
    wprep_k<<<(256 * 256 + 255) / 256, 256>>>(W_c1, btp, Hh, 256);
    bn_zero_k<<<1, 256>>>();
    gemm_mma_k<2, 1, true><<<mgrid, 256, GEMM_SMEM>>>(nullptr, acc0p, btp, b_c1, acc1p, Nn, 256);
    bn_final_k<<<1, 256>>>(g_c, beta_c, 1.f / Nn);

    head2_k<<<(Nn + 255) / 256, 256, H2_SMEM>>>(acc1p, W_c2, b_c2, out, Nn);
}